// round 1
// baseline (speedup 1.0000x reference)
#include <cuda_runtime.h>
#include <cstddef>

#define NN 100000
#define EE 640000
#define PP 640000
#define DD 128
#define GG 128
#define LL 3
#define BN_EPS 1e-5f

// ---------------- device scratch (no dynamic allocation allowed) ----------------
__device__ float g_z2 [(size_t)EE * DD];   // 327 MB : z after encoder
__device__ float g_ee [(size_t)EE * DD];   // 327 MB : z_pre, then per-layer edge_emb
__device__ float g_hin[(size_t)NN * DD];   // 51 MB
__device__ float g_agg[(size_t)NN * DD];   // 51 MB
__device__ float g_t2 [(size_t)NN * 2 * DD]; // 102 MB
__device__ float g_vn [GG * DD];
__device__ float g_vt [GG * DD];

// ---------------- helpers ----------------
__device__ __forceinline__ void red_add_v4(float* p, float4 v) {
    asm volatile("red.global.add.v4.f32 [%0], {%1,%2,%3,%4};"
                 :: "l"(p), "f"(v.x), "f"(v.y), "f"(v.z), "f"(v.w) : "memory");
}

__global__ void k_zero(float4* __restrict__ p, int n4) {
    int i = blockIdx.x * blockDim.x + threadIdx.x;
    if (i < n4) p[i] = make_float4(0.f, 0.f, 0.f, 0.f);
}

__global__ void k_init_h(const int* __restrict__ xn, const float* __restrict__ emb,
                         float* __restrict__ h) {
    int i = blockIdx.x * blockDim.x + threadIdx.x;  // over NN*32 float4 slots
    if (i >= NN * 32) return;
    int row = i >> 5, q = (i & 31) << 2;
    float4 v = *(const float4*)(emb + (size_t)xn[row] * DD + q);
    *(float4*)(h + (size_t)row * DD + q) = v;
}

__global__ void k_init_vn(const float* __restrict__ emb, float* __restrict__ vn) {
    int i = blockIdx.x * blockDim.x + threadIdx.x;
    if (i < GG * DD) vn[i] = emb[i & (DD - 1)];
}

// z_pre[seg] += z_init[pos_index[p]] * pos_enc[p]   (warp per p, v4 red)
__global__ void k_pos_scatter(const int* __restrict__ pidx, const float* __restrict__ penc,
                              const int* __restrict__ pbatch, const float* __restrict__ zinit,
                              float* __restrict__ zpre) {
    int t = blockIdx.x * blockDim.x + threadIdx.x;
    int p = t >> 5, lane = t & 31;
    if (p >= PP) return;
    int zi = __ldg(pidx + p);
    float w = __ldg(penc + p);
    int seg = __ldg(pbatch + p);
    float4 v = *(const float4*)(zinit + (size_t)zi * DD + lane * 4);
    v.x *= w; v.y *= w; v.z *= w; v.w *= w;
    red_add_v4(zpre + (size_t)seg * DD + lane * 4, v);
}

// in-place BN(128 cols)+ReLU over [rows,128]
__global__ void k_bn_relu128(float* __restrict__ x, const float* __restrict__ bn, int n4) {
    __shared__ float ss[DD], tt[DD];
    int tid = threadIdx.x;
    if (tid < DD) {
        float s = bn[tid] * rsqrtf(bn[3 * DD + tid] + BN_EPS);
        ss[tid] = s;
        tt[tid] = bn[DD + tid] - bn[2 * DD + tid] * s;
    }
    __syncthreads();
    int i = blockIdx.x * blockDim.x + tid;
    if (i >= n4) return;
    int q = (i & 31) << 2;
    float4 v = *(float4*)(x + (size_t)i * 4);
    v.x = fmaxf(v.x * ss[q + 0] + tt[q + 0], 0.f);
    v.y = fmaxf(v.y * ss[q + 1] + tt[q + 1], 0.f);
    v.z = fmaxf(v.z * ss[q + 2] + tt[q + 2], 0.f);
    v.w = fmaxf(v.w * ss[q + 3] + tt[q + 3], 0.f);
    *(float4*)(x + (size_t)i * 4) = v;
}

// h_in = h + vn[batch]
__global__ void k_hin(const float* __restrict__ h, const float* __restrict__ vn,
                      const int* __restrict__ batch, float* __restrict__ hin) {
    int i = blockIdx.x * blockDim.x + threadIdx.x;
    if (i >= NN * 32) return;
    int row = i >> 5, q = (i & 31) << 2;
    int g = __ldg(batch + row);
    float4 a = *(const float4*)(h + (size_t)row * DD + q);
    float4 b = *(const float4*)(vn + (size_t)g * DD + q);
    a.x += b.x; a.y += b.y; a.z += b.z; a.w += b.w;
    *(float4*)(hin + (size_t)row * DD + q) = a;
}

// agg = (1+eps)*hin + agg   (in place)
__global__ void k_make_t(const float* __restrict__ hin, float* __restrict__ agg,
                         const float* __restrict__ epsp) {
    int i = blockIdx.x * blockDim.x + threadIdx.x;
    if (i >= NN * 32) return;
    float c = 1.0f + __ldg(epsp);
    float4 a = ((const float4*)agg)[i];
    float4 hh = ((const float4*)hin)[i];
    a.x = fmaf(c, hh.x, a.x);
    a.y = fmaf(c, hh.y, a.y);
    a.z = fmaf(c, hh.z, a.z);
    a.w = fmaf(c, hh.w, a.w);
    ((float4*)agg)[i] = a;
}

// agg[dst] += relu(hin[src] + ee)   (warp per edge, v4 red)
__global__ void k_scatter(const int* __restrict__ src, const int* __restrict__ dst,
                          const float* __restrict__ hin, const float* __restrict__ ee,
                          float* __restrict__ agg) {
    int t = blockIdx.x * blockDim.x + threadIdx.x;
    int e = t >> 5, lane = t & 31;
    if (e >= EE) return;
    int s = __ldg(src + e), d = __ldg(dst + e);
    float4 hv = *(const float4*)(hin + (size_t)s * DD + lane * 4);
    float4 ev = *(const float4*)(ee + (size_t)e * DD + lane * 4);
    float4 m;
    m.x = fmaxf(hv.x + ev.x, 0.f);
    m.y = fmaxf(hv.y + ev.y, 0.f);
    m.z = fmaxf(hv.z + ev.z, 0.f);
    m.w = fmaxf(hv.w + ev.w, 0.f);
    red_add_v4(agg + (size_t)d * DD + lane * 4, m);
}

// ---------------- register-tiled SGEMM, C = act(BN(A@B + bias)) ----------------
// BM=BN=128, BK=8, 256 threads, 8x8 micro-tile
__global__ __launch_bounds__(256)
void sgemm_bn(const float* __restrict__ A, const float* __restrict__ B,
              const float* __restrict__ bias, const float* __restrict__ bn,
              float* __restrict__ C, int M, int K, int Nc, int relu) {
    __shared__ float As[8][128];
    __shared__ float Bs[8][128];
    int tid = threadIdx.x;
    int row0 = blockIdx.x * 128;
    int col0 = blockIdx.y * 128;
    int aRow = tid >> 1, aCol = (tid & 1) << 2;
    int bRow = tid >> 5, bCol = (tid & 31) << 2;
    int ty = tid >> 4, tx = tid & 15;

    float acc[8][8];
#pragma unroll
    for (int i = 0; i < 8; i++)
#pragma unroll
        for (int j = 0; j < 8; j++) acc[i][j] = 0.f;

    for (int k0 = 0; k0 < K; k0 += 8) {
        float4 av = make_float4(0.f, 0.f, 0.f, 0.f);
        int gr = row0 + aRow;
        if (gr < M) av = *(const float4*)(A + (size_t)gr * K + k0 + aCol);
        As[aCol + 0][aRow] = av.x;
        As[aCol + 1][aRow] = av.y;
        As[aCol + 2][aRow] = av.z;
        As[aCol + 3][aRow] = av.w;
        *(float4*)&Bs[bRow][bCol] =
            *(const float4*)(B + (size_t)(k0 + bRow) * Nc + col0 + bCol);
        __syncthreads();
#pragma unroll
        for (int k = 0; k < 8; k++) {
            float a[8], b[8];
            *(float4*)(a)     = *(const float4*)&As[k][ty * 8];
            *(float4*)(a + 4) = *(const float4*)&As[k][ty * 8 + 4];
            *(float4*)(b)     = *(const float4*)&Bs[k][tx * 8];
            *(float4*)(b + 4) = *(const float4*)&Bs[k][tx * 8 + 4];
#pragma unroll
            for (int i = 0; i < 8; i++)
#pragma unroll
                for (int j = 0; j < 8; j++) acc[i][j] = fmaf(a[i], b[j], acc[i][j]);
        }
        __syncthreads();
    }

    float sj[8], tj[8];
#pragma unroll
    for (int j = 0; j < 8; j++) {
        int c = col0 + tx * 8 + j;
        float s = bn[c] * rsqrtf(bn[3 * Nc + c] + BN_EPS);
        sj[j] = s;
        tj[j] = bn[Nc + c] + (bias[c] - bn[2 * Nc + c]) * s;
    }
#pragma unroll
    for (int i = 0; i < 8; i++) {
        int gr = row0 + ty * 8 + i;
        if (gr >= M) continue;
        float v[8];
#pragma unroll
        for (int j = 0; j < 8; j++) {
            float y = acc[i][j] * sj[j] + tj[j];
            v[j] = relu ? fmaxf(y, 0.f) : y;
        }
        *(float4*)(C + (size_t)gr * Nc + col0 + tx * 8)     = make_float4(v[0], v[1], v[2], v[3]);
        *(float4*)(C + (size_t)gr * Nc + col0 + tx * 8 + 4) = make_float4(v[4], v[5], v[6], v[7]);
    }
}

// edge_emb GEMM: C = z2@Wp + bp + edge_attr@We + be  (K=128, Nc=128 fixed)
__global__ __launch_bounds__(256)
void sgemm_edge(const float* __restrict__ A, const float* __restrict__ B,
                const float* __restrict__ bp, const float* __restrict__ be,
                const float* __restrict__ Ae, const float* __restrict__ We7,
                float* __restrict__ C, int M) {
    __shared__ float As[8][128];
    __shared__ float Bs[8][128];
    __shared__ float AeS[128][8];
    __shared__ float WeS[7][128];
    int tid = threadIdx.x;
    int row0 = blockIdx.x * 128;

    for (int i = tid; i < 128 * 7; i += 256) {
        int r = i / 7, c = i % 7;
        int gr = row0 + r;
        AeS[r][c] = (gr < M) ? Ae[(size_t)gr * 7 + c] : 0.f;
    }
    for (int i = tid; i < 7 * 128; i += 256) WeS[i / 128][i % 128] = We7[i];

    int aRow = tid >> 1, aCol = (tid & 1) << 2;
    int bRow = tid >> 5, bCol = (tid & 31) << 2;
    int ty = tid >> 4, tx = tid & 15;

    float acc[8][8];
#pragma unroll
    for (int i = 0; i < 8; i++)
#pragma unroll
        for (int j = 0; j < 8; j++) acc[i][j] = 0.f;

    for (int k0 = 0; k0 < 128; k0 += 8) {
        float4 av = make_float4(0.f, 0.f, 0.f, 0.f);
        int gr = row0 + aRow;
        if (gr < M) av = *(const float4*)(A + (size_t)gr * 128 + k0 + aCol);
        As[aCol + 0][aRow] = av.x;
        As[aCol + 1][aRow] = av.y;
        As[aCol + 2][aRow] = av.z;
        As[aCol + 3][aRow] = av.w;
        *(float4*)&Bs[bRow][bCol] =
            *(const float4*)(B + (size_t)(k0 + bRow) * 128 + bCol);
        __syncthreads();
#pragma unroll
        for (int k = 0; k < 8; k++) {
            float a[8], b[8];
            *(float4*)(a)     = *(const float4*)&As[k][ty * 8];
            *(float4*)(a + 4) = *(const float4*)&As[k][ty * 8 + 4];
            *(float4*)(b)     = *(const float4*)&Bs[k][tx * 8];
            *(float4*)(b + 4) = *(const float4*)&Bs[k][tx * 8 + 4];
#pragma unroll
            for (int i = 0; i < 8; i++)
#pragma unroll
                for (int j = 0; j < 8; j++) acc[i][j] = fmaf(a[i], b[j], acc[i][j]);
        }
        __syncthreads();
    }

    float bj[8];
#pragma unroll
    for (int j = 0; j < 8; j++) {
        int c = tx * 8 + j;
        bj[j] = bp[c] + be[c];
    }
#pragma unroll
    for (int i = 0; i < 8; i++) {
        int r = ty * 8 + i;
        int gr = row0 + r;
        if (gr >= M) continue;
        float a7[7];
#pragma unroll
        for (int k = 0; k < 7; k++) a7[k] = AeS[r][k];
        float v[8];
#pragma unroll
        for (int j = 0; j < 8; j++) {
            float y = acc[i][j] + bj[j];
#pragma unroll
            for (int k = 0; k < 7; k++) y = fmaf(a7[k], WeS[k][tx * 8 + j], y);
            v[j] = y;
        }
        *(float4*)(C + (size_t)gr * 128 + tx * 8)     = make_float4(v[0], v[1], v[2], v[3]);
        *(float4*)(C + (size_t)gr * 128 + tx * 8 + 4) = make_float4(v[4], v[5], v[6], v[7]);
    }
}

// per-graph reduction: vt[g] = sum_{batch==g} hin + vn[g]  (batch sorted)
__global__ void k_vn_agg(const float* __restrict__ hin, const int* __restrict__ batch,
                         const float* __restrict__ vn, float* __restrict__ vt) {
    int g = blockIdx.x, c = threadIdx.x;
    int lo = 0, hi = NN;
    while (lo < hi) { int m = (lo + hi) >> 1; if (batch[m] < g) lo = m + 1; else hi = m; }
    int start = lo;
    lo = start; hi = NN;
    while (lo < hi) { int m = (lo + hi) >> 1; if (batch[m] < g + 1) lo = m + 1; else hi = m; }
    int end = lo;
    float sum = 0.f;
    for (int i = start; i < end; i++) sum += hin[(size_t)i * DD + c];
    vt[g * DD + c] = sum + vn[g * DD + c];
}

// vn = relu(bn2(relu(bn1(vt@W1+b1))@W2+b2)) : tiny, one block per graph
__global__ void k_vn_mlp(const float* __restrict__ vt,
                         const float* __restrict__ W1, const float* __restrict__ b1,
                         const float* __restrict__ bn1,
                         const float* __restrict__ W2, const float* __restrict__ b2,
                         const float* __restrict__ bn2, float* __restrict__ vn) {
    __shared__ float xr[DD];
    __shared__ float tr[2 * DD];
    int g = blockIdx.x, tid = threadIdx.x;
    if (tid < DD) xr[tid] = vt[g * DD + tid];
    __syncthreads();
    float acc = b1[tid];
#pragma unroll 8
    for (int k = 0; k < DD; k++) acc = fmaf(xr[k], W1[(size_t)k * 2 * DD + tid], acc);
    float s = bn1[tid] * rsqrtf(bn1[3 * 2 * DD + tid] + BN_EPS);
    acc = (acc - bn1[2 * 2 * DD + tid]) * s + bn1[2 * DD + tid];
    tr[tid] = fmaxf(acc, 0.f);
    __syncthreads();
    if (tid < DD) {
        float a2 = b2[tid];
#pragma unroll 8
        for (int k = 0; k < 2 * DD; k++) a2 = fmaf(tr[k], W2[(size_t)k * DD + tid], a2);
        float s2 = bn2[tid] * rsqrtf(bn2[3 * DD + tid] + BN_EPS);
        a2 = (a2 - bn2[2 * DD + tid]) * s2 + bn2[DD + tid];
        vn[g * DD + tid] = fmaxf(a2, 0.f);
    }
}

// ---------------- host launcher ----------------
extern "C" void kernel_launch(void* const* d_in, const int* in_sizes, int n_in,
                              void* d_out, int out_size) {
    const int*   x_node     = (const int*)d_in[0];
    const int*   edge_index = (const int*)d_in[1];
    const float* edge_attr  = (const float*)d_in[2];
    const int*   batch      = (const int*)d_in[3];
    const int*   pos_index  = (const int*)d_in[4];
    const float* pos_enc    = (const float*)d_in[5];
    const int*   pos_batch  = (const int*)d_in[6];
    const float* node_emb   = (const float*)d_in[7];
    const float* z_init     = (const float*)d_in[8];
    const float* ze_bn1     = (const float*)d_in[9];
    const float* ze_W       = (const float*)d_in[10];
    const float* ze_b       = (const float*)d_in[11];
    const float* ze_bn2     = (const float*)d_in[12];
    const float* vn_emb     = (const float*)d_in[13];
    const float* conv_We    = (const float*)d_in[14];
    const float* conv_be    = (const float*)d_in[15];
    const float* conv_Wp    = (const float*)d_in[16];
    const float* conv_bp    = (const float*)d_in[17];
    const float* conv_W1    = (const float*)d_in[18];
    const float* conv_b1    = (const float*)d_in[19];
    const float* conv_bn    = (const float*)d_in[20];
    const float* conv_W2    = (const float*)d_in[21];
    const float* conv_b2    = (const float*)d_in[22];
    const float* conv_eps   = (const float*)d_in[23];
    const float* layer_bn   = (const float*)d_in[24];
    const float* vn_W1      = (const float*)d_in[25];
    const float* vn_b1      = (const float*)d_in[26];
    const float* vn_bn1     = (const float*)d_in[27];
    const float* vn_W2      = (const float*)d_in[28];
    const float* vn_b2      = (const float*)d_in[29];
    const float* vn_bn2     = (const float*)d_in[30];

    float *z2, *ee, *hin, *agg, *t2, *vn, *vt;
    cudaGetSymbolAddress((void**)&z2,  g_z2);
    cudaGetSymbolAddress((void**)&ee,  g_ee);
    cudaGetSymbolAddress((void**)&hin, g_hin);
    cudaGetSymbolAddress((void**)&agg, g_agg);
    cudaGetSymbolAddress((void**)&t2,  g_t2);
    cudaGetSymbolAddress((void**)&vn,  g_vn);
    cudaGetSymbolAddress((void**)&vt,  g_vt);

    float* h = (float*)d_out;

    // ---- z encoder (once) ----
    {
        int n4 = EE * DD / 4;
        k_zero<<<(n4 + 255) / 256, 256>>>((float4*)ee, n4);
    }
    k_pos_scatter<<<(PP * 32 + 255) / 256, 256>>>(pos_index, pos_enc, pos_batch, z_init, ee);
    {
        int n4 = EE * DD / 4;
        k_bn_relu128<<<(n4 + 255) / 256, 256>>>(ee, ze_bn1, n4);
    }
    {
        dim3 g(EE / 128, 1);
        sgemm_bn<<<g, 256>>>(ee, ze_W, ze_b, ze_bn2, z2, EE, 128, 128, 1);
    }
    k_init_h<<<(NN * 32 + 255) / 256, 256>>>(x_node, node_emb, h);
    k_init_vn<<<(GG * DD + 255) / 256, 256>>>(vn_emb, vn);

    const int* srcp = edge_index;
    const int* dstp = edge_index + EE;

    for (int l = 0; l < LL; l++) {
        k_hin<<<(NN * 32 + 255) / 256, 256>>>(h, vn, batch, hin);
        {
            dim3 g(EE / 128, 1);
            sgemm_edge<<<g, 256>>>(z2, conv_Wp + (size_t)l * DD * DD, conv_bp + l * DD,
                                   conv_be + l * DD, edge_attr, conv_We + (size_t)l * 7 * DD,
                                   ee, EE);
        }
        {
            int n4 = NN * DD / 4;
            k_zero<<<(n4 + 255) / 256, 256>>>((float4*)agg, n4);
        }
        k_scatter<<<(EE * 32 + 255) / 256, 256>>>(srcp, dstp, hin, ee, agg);
        k_make_t<<<(NN * 32 + 255) / 256, 256>>>(hin, agg, conv_eps + l);
        {
            dim3 g((NN + 127) / 128, 2);
            sgemm_bn<<<g, 256>>>(agg, conv_W1 + (size_t)l * DD * 2 * DD, conv_b1 + l * 2 * DD,
                                 conv_bn + (size_t)l * 4 * 2 * DD, t2, NN, DD, 2 * DD, 1);
        }
        {
            dim3 g((NN + 127) / 128, 1);
            sgemm_bn<<<g, 256>>>(t2, conv_W2 + (size_t)l * 2 * DD * DD, conv_b2 + l * DD,
                                 layer_bn + (size_t)l * 4 * DD, h, NN, 2 * DD, DD,
                                 (l < LL - 1) ? 1 : 0);
        }
        if (l < LL - 1) {
            k_vn_agg<<<GG, DD>>>(hin, batch, vn, vt);
            k_vn_mlp<<<GG, 256>>>(vt, vn_W1 + (size_t)l * DD * 2 * DD, vn_b1 + l * 2 * DD,
                                  vn_bn1 + (size_t)l * 4 * 2 * DD,
                                  vn_W2 + (size_t)l * 2 * DD * DD, vn_b2 + l * DD,
                                  vn_bn2 + (size_t)l * 4 * DD, vn);
        }
    }
}

// round 2
// speedup vs baseline: 1.9592x; 1.9592x over previous
#include <cuda_runtime.h>
#include <cstddef>

#define NN 100000
#define EE 640000
#define PP 640000
#define DD 128
#define GG 128
#define LL 3
#define BN_EPS 1e-5f

// ---------------- device scratch ----------------
__device__ float g_z2 [(size_t)EE * DD];
__device__ float g_ee [(size_t)EE * DD];
__device__ float g_hin[(size_t)NN * DD];
__device__ float g_agg[(size_t)NN * DD];
__device__ float g_t2 [(size_t)NN * 2 * DD];
__device__ float g_vn [GG * DD];
__device__ float g_vt [GG * DD];

// ---------------- helpers ----------------
__device__ __forceinline__ void red_add_v4(float* p, float4 v) {
    asm volatile("red.global.add.v4.f32 [%0], {%1,%2,%3,%4};"
                 :: "l"(p), "f"(v.x), "f"(v.y), "f"(v.z), "f"(v.w) : "memory");
}
__device__ __forceinline__ unsigned f2tf(float f) {
    unsigned u;
    asm("cvt.rna.tf32.f32 %0, %1;" : "=r"(u) : "f"(f));
    return u;
}
__device__ __forceinline__ void mma_tf32(float* c, const unsigned* a, const unsigned* b) {
    asm volatile("mma.sync.aligned.m16n8k8.row.col.f32.tf32.tf32.f32 "
                 "{%0,%1,%2,%3}, {%4,%5,%6,%7}, {%8,%9}, {%0,%1,%2,%3};"
                 : "+f"(c[0]), "+f"(c[1]), "+f"(c[2]), "+f"(c[3])
                 : "r"(a[0]), "r"(a[1]), "r"(a[2]), "r"(a[3]),
                   "r"(b[0]), "r"(b[1]));
}

__global__ void k_zero(float4* __restrict__ p, int n4) {
    int i = blockIdx.x * blockDim.x + threadIdx.x;
    if (i < n4) p[i] = make_float4(0.f, 0.f, 0.f, 0.f);
}

__global__ void k_init_h(const int* __restrict__ xn, const float* __restrict__ emb,
                         float* __restrict__ h) {
    int i = blockIdx.x * blockDim.x + threadIdx.x;
    if (i >= NN * 32) return;
    int row = i >> 5, q = (i & 31) << 2;
    float4 v = *(const float4*)(emb + (size_t)xn[row] * DD + q);
    *(float4*)(h + (size_t)row * DD + q) = v;
}

__global__ void k_init_vn(const float* __restrict__ emb, float* __restrict__ vn) {
    int i = blockIdx.x * blockDim.x + threadIdx.x;
    if (i < GG * DD) vn[i] = emb[i & (DD - 1)];
}

__global__ void k_pos_scatter(const int* __restrict__ pidx, const float* __restrict__ penc,
                              const int* __restrict__ pbatch, const float* __restrict__ zinit,
                              float* __restrict__ zpre) {
    int t = blockIdx.x * blockDim.x + threadIdx.x;
    int p = t >> 5, lane = t & 31;
    if (p >= PP) return;
    int zi = __ldg(pidx + p);
    float w = __ldg(penc + p);
    int seg = __ldg(pbatch + p);
    float4 v = *(const float4*)(zinit + (size_t)zi * DD + lane * 4);
    v.x *= w; v.y *= w; v.z *= w; v.w *= w;
    red_add_v4(zpre + (size_t)seg * DD + lane * 4, v);
}

// hin = h + vn[batch];  agg = (1+eps)*hin
__global__ void k_hin_agg(const float* __restrict__ h, const float* __restrict__ vn,
                          const int* __restrict__ batch, const float* __restrict__ epsp,
                          float* __restrict__ hin, float* __restrict__ agg) {
    int i = blockIdx.x * blockDim.x + threadIdx.x;
    if (i >= NN * 32) return;
    int row = i >> 5, q = (i & 31) << 2;
    int g = __ldg(batch + row);
    float c = 1.0f + __ldg(epsp);
    float4 a = *(const float4*)(h + (size_t)row * DD + q);
    float4 b = *(const float4*)(vn + (size_t)g * DD + q);
    a.x += b.x; a.y += b.y; a.z += b.z; a.w += b.w;
    *(float4*)(hin + (size_t)row * DD + q) = a;
    float4 e = make_float4(c * a.x, c * a.y, c * a.z, c * a.w);
    *(float4*)(agg + (size_t)row * DD + q) = e;
}

// agg[dst] += relu(hin[src] + ee)
__global__ void k_scatter(const int* __restrict__ src, const int* __restrict__ dst,
                          const float* __restrict__ hin, const float* __restrict__ ee,
                          float* __restrict__ agg) {
    int t = blockIdx.x * blockDim.x + threadIdx.x;
    int e = t >> 5, lane = t & 31;
    if (e >= EE) return;
    int s = __ldg(src + e), d = __ldg(dst + e);
    float4 hv = *(const float4*)(hin + (size_t)s * DD + lane * 4);
    float4 ev = *(const float4*)(ee + (size_t)e * DD + lane * 4);
    float4 m;
    m.x = fmaxf(hv.x + ev.x, 0.f);
    m.y = fmaxf(hv.y + ev.y, 0.f);
    m.z = fmaxf(hv.z + ev.z, 0.f);
    m.w = fmaxf(hv.w + ev.w, 0.f);
    red_add_v4(agg + (size_t)d * DD + lane * 4, m);
}

// ---------------- tf32 tensor-core GEMM ----------------
// C[M,Nc] = epi( act_a(A)[M,K] @ B[K,Nc] )
// block tile 128x128, k-chunk 64, 8 warps (2m x 4n), warp tile 64x32
// smem: As [128][68] tf32, Bs [64][132] tf32 (dynamic, conflict-free padding)
#define AS_S 68
#define BS_S 132
#define TG_SMEM ((128 * AS_S + 64 * BS_S) * 4)

__global__ __launch_bounds__(256, 2)
void tgemm(const float* __restrict__ A, const float* __restrict__ B,
           int M, int K, int Nc,
           const float* __restrict__ aBn,     // nullable: BN(4,K)+relu applied to A
           const float* __restrict__ bias, const float* __restrict__ bias2,
           const float* __restrict__ bn,      // nullable: BN(4,Nc) epilogue
           int relu,
           const float* __restrict__ Ae, const float* __restrict__ We7,  // nullable edge extras
           float* __restrict__ C) {
    extern __shared__ unsigned smem[];
    unsigned* As = smem;
    unsigned* Bs = smem + 128 * AS_S;
    __shared__ float AeS[128 * 8];
    __shared__ float WeS[7 * BS_S];

    const int tid = threadIdx.x;
    const int lane = tid & 31, wid = tid >> 5;
    const int g = lane >> 2, t = lane & 3;
    const int warp_m = wid & 1, warp_n = wid >> 1;
    const int row0 = blockIdx.x * 128;
    const int col0 = blockIdx.y * 128;
    const bool edge = (Ae != nullptr);

    if (edge) {
        for (int i = tid; i < 128 * 7; i += 256) {
            int r = i / 7, c = i % 7;
            int gr = row0 + r;
            AeS[r * 8 + c] = (gr < M) ? Ae[(size_t)gr * 7 + c] : 0.f;
        }
        for (int i = tid; i < 7 * 128; i += 256)
            WeS[(i >> 7) * BS_S + (i & 127)] = We7[i];
    }

    float acc[4][4][4];
#pragma unroll
    for (int mt = 0; mt < 4; mt++)
#pragma unroll
        for (int nt = 0; nt < 4; nt++)
#pragma unroll
            for (int q = 0; q < 4; q++) acc[mt][nt][q] = 0.f;

    const int arow = tid >> 4;          // 0..15
    const int acol = (tid & 15) << 2;   // 0..60
    const int brow = tid >> 5;          // 0..7
    const int bcol = (tid & 31) << 2;   // 0..124

    for (int k0 = 0; k0 < K; k0 += 64) {
        __syncthreads();
        // load A chunk 128x64 (+optional BN/relu), cvt tf32
#pragma unroll
        for (int p = 0; p < 8; p++) {
            int r = arow + p * 16;
            int gr = row0 + r;
            float4 v = make_float4(0.f, 0.f, 0.f, 0.f);
            if (gr < M) v = *(const float4*)(A + (size_t)gr * K + k0 + acol);
            if (aBn) {
                int kk = k0 + acol;
                float vv[4] = {v.x, v.y, v.z, v.w};
#pragma unroll
                for (int q = 0; q < 4; q++) {
                    int kq = kk + q;
                    float s = aBn[kq] * rsqrtf(aBn[3 * K + kq] + BN_EPS);
                    float bb = aBn[K + kq] - aBn[2 * K + kq] * s;
                    vv[q] = fmaxf(vv[q] * s + bb, 0.f);
                }
                v.x = vv[0]; v.y = vv[1]; v.z = vv[2]; v.w = vv[3];
            }
            unsigned* d = As + r * AS_S + acol;
            d[0] = f2tf(v.x); d[1] = f2tf(v.y); d[2] = f2tf(v.z); d[3] = f2tf(v.w);
        }
        // load B chunk 64x128, cvt tf32
#pragma unroll
        for (int p = 0; p < 8; p++) {
            int r = brow + p * 8;
            float4 v = *(const float4*)(B + (size_t)(k0 + r) * Nc + col0 + bcol);
            unsigned* d = Bs + r * BS_S + bcol;
            d[0] = f2tf(v.x); d[1] = f2tf(v.y); d[2] = f2tf(v.z); d[3] = f2tf(v.w);
        }
        __syncthreads();

#pragma unroll
        for (int kk = 0; kk < 64; kk += 8) {
            unsigned af[4][4], bf[4][2];
#pragma unroll
            for (int mt = 0; mt < 4; mt++) {
                int mb = warp_m * 64 + mt * 16;
                af[mt][0] = As[(mb + g) * AS_S + kk + t];
                af[mt][1] = As[(mb + g + 8) * AS_S + kk + t];
                af[mt][2] = As[(mb + g) * AS_S + kk + t + 4];
                af[mt][3] = As[(mb + g + 8) * AS_S + kk + t + 4];
            }
#pragma unroll
            for (int nt = 0; nt < 4; nt++) {
                int n = warp_n * 32 + nt * 8 + g;
                bf[nt][0] = Bs[(kk + t) * BS_S + n];
                bf[nt][1] = Bs[(kk + t + 4) * BS_S + n];
            }
#pragma unroll
            for (int mt = 0; mt < 4; mt++)
#pragma unroll
                for (int nt = 0; nt < 4; nt++)
                    mma_tf32(acc[mt][nt], af[mt], bf[nt]);
        }
    }

    // epilogue scale/shift per owned column
    float sc[8], sh[8];
#pragma unroll
    for (int nt = 0; nt < 4; nt++)
#pragma unroll
        for (int hh = 0; hh < 2; hh++) {
            int c = col0 + warp_n * 32 + nt * 8 + 2 * t + hh;
            float bsum = bias ? bias[c] : 0.f;
            if (bias2) bsum += bias2[c];
            if (bn) {
                float s = bn[c] * rsqrtf(bn[3 * Nc + c] + BN_EPS);
                sc[nt * 2 + hh] = s;
                sh[nt * 2 + hh] = bn[Nc + c] + (bsum - bn[2 * Nc + c]) * s;
            } else {
                sc[nt * 2 + hh] = 1.f;
                sh[nt * 2 + hh] = bsum;
            }
        }

#pragma unroll
    for (int mt = 0; mt < 4; mt++) {
#pragma unroll
        for (int half = 0; half < 2; half++) {
            int lr = warp_m * 64 + mt * 16 + g + 8 * half;
            int gr = row0 + lr;
            if (gr >= M) continue;
            float a7[7];
            if (edge) {
#pragma unroll
                for (int k = 0; k < 7; k++) a7[k] = AeS[lr * 8 + k];
            }
#pragma unroll
            for (int nt = 0; nt < 4; nt++) {
                float y0 = acc[mt][nt][half * 2 + 0] * sc[nt * 2 + 0] + sh[nt * 2 + 0];
                float y1 = acc[mt][nt][half * 2 + 1] * sc[nt * 2 + 1] + sh[nt * 2 + 1];
                int cb = warp_n * 32 + nt * 8 + 2 * t;
                if (edge) {
#pragma unroll
                    for (int k = 0; k < 7; k++) {
                        y0 = fmaf(a7[k], WeS[k * BS_S + cb], y0);
                        y1 = fmaf(a7[k], WeS[k * BS_S + cb + 1], y1);
                    }
                }
                if (relu) { y0 = fmaxf(y0, 0.f); y1 = fmaxf(y1, 0.f); }
                *(float2*)(C + (size_t)gr * Nc + col0 + cb) = make_float2(y0, y1);
            }
        }
    }
}

// per-graph reduction: vt[g] = sum_{batch==g} hin + vn[g]
__global__ void k_vn_agg(const float* __restrict__ hin, const int* __restrict__ batch,
                         const float* __restrict__ vn, float* __restrict__ vt) {
    int g = blockIdx.x, c = threadIdx.x;
    int lo = 0, hi = NN;
    while (lo < hi) { int m = (lo + hi) >> 1; if (batch[m] < g) lo = m + 1; else hi = m; }
    int start = lo;
    lo = start; hi = NN;
    while (lo < hi) { int m = (lo + hi) >> 1; if (batch[m] < g + 1) lo = m + 1; else hi = m; }
    int end = lo;
    float sum = 0.f;
    for (int i = start; i < end; i++) sum += hin[(size_t)i * DD + c];
    vt[g * DD + c] = sum + vn[g * DD + c];
}

__global__ void k_vn_mlp(const float* __restrict__ vt,
                         const float* __restrict__ W1, const float* __restrict__ b1,
                         const float* __restrict__ bn1,
                         const float* __restrict__ W2, const float* __restrict__ b2,
                         const float* __restrict__ bn2, float* __restrict__ vn) {
    __shared__ float xr[DD];
    __shared__ float tr[2 * DD];
    int g = blockIdx.x, tid = threadIdx.x;
    if (tid < DD) xr[tid] = vt[g * DD + tid];
    __syncthreads();
    float acc = b1[tid];
#pragma unroll 8
    for (int k = 0; k < DD; k++) acc = fmaf(xr[k], W1[(size_t)k * 2 * DD + tid], acc);
    float s = bn1[tid] * rsqrtf(bn1[3 * 2 * DD + tid] + BN_EPS);
    acc = (acc - bn1[2 * 2 * DD + tid]) * s + bn1[2 * DD + tid];
    tr[tid] = fmaxf(acc, 0.f);
    __syncthreads();
    if (tid < DD) {
        float a2 = b2[tid];
#pragma unroll 8
        for (int k = 0; k < 2 * DD; k++) a2 = fmaf(tr[k], W2[(size_t)k * DD + tid], a2);
        float s2 = bn2[tid] * rsqrtf(bn2[3 * DD + tid] + BN_EPS);
        a2 = (a2 - bn2[2 * DD + tid]) * s2 + bn2[DD + tid];
        vn[g * DD + tid] = fmaxf(a2, 0.f);
    }
}

// ---------------- host launcher ----------------
extern "C" void kernel_launch(void* const* d_in, const int* in_sizes, int n_in,
                              void* d_out, int out_size) {
    const int*   x_node     = (const int*)d_in[0];
    const int*   edge_index = (const int*)d_in[1];
    const float* edge_attr  = (const float*)d_in[2];
    const int*   batch      = (const int*)d_in[3];
    const int*   pos_index  = (const int*)d_in[4];
    const float* pos_enc    = (const float*)d_in[5];
    const int*   pos_batch  = (const int*)d_in[6];
    const float* node_emb   = (const float*)d_in[7];
    const float* z_init     = (const float*)d_in[8];
    const float* ze_bn1     = (const float*)d_in[9];
    const float* ze_W       = (const float*)d_in[10];
    const float* ze_b       = (const float*)d_in[11];
    const float* ze_bn2     = (const float*)d_in[12];
    const float* vn_emb     = (const float*)d_in[13];
    const float* conv_We    = (const float*)d_in[14];
    const float* conv_be    = (const float*)d_in[15];
    const float* conv_Wp    = (const float*)d_in[16];
    const float* conv_bp    = (const float*)d_in[17];
    const float* conv_W1    = (const float*)d_in[18];
    const float* conv_b1    = (const float*)d_in[19];
    const float* conv_bn    = (const float*)d_in[20];
    const float* conv_W2    = (const float*)d_in[21];
    const float* conv_b2    = (const float*)d_in[22];
    const float* conv_eps   = (const float*)d_in[23];
    const float* layer_bn   = (const float*)d_in[24];
    const float* vn_W1      = (const float*)d_in[25];
    const float* vn_b1      = (const float*)d_in[26];
    const float* vn_bn1     = (const float*)d_in[27];
    const float* vn_W2      = (const float*)d_in[28];
    const float* vn_b2      = (const float*)d_in[29];
    const float* vn_bn2     = (const float*)d_in[30];

    float *z2, *ee, *hin, *agg, *t2, *vn, *vt;
    cudaGetSymbolAddress((void**)&z2,  g_z2);
    cudaGetSymbolAddress((void**)&ee,  g_ee);
    cudaGetSymbolAddress((void**)&hin, g_hin);
    cudaGetSymbolAddress((void**)&agg, g_agg);
    cudaGetSymbolAddress((void**)&t2,  g_t2);
    cudaGetSymbolAddress((void**)&vn,  g_vn);
    cudaGetSymbolAddress((void**)&vt,  g_vt);

    cudaFuncSetAttribute(tgemm, cudaFuncAttributeMaxDynamicSharedMemorySize, TG_SMEM);

    float* h = (float*)d_out;

    // ---- z encoder (once) ----
    {
        int n4 = EE * DD / 4;
        k_zero<<<(n4 + 255) / 256, 256>>>((float4*)ee, n4);
    }
    k_pos_scatter<<<(PP * 32 + 255) / 256, 256>>>(pos_index, pos_enc, pos_batch, z_init, ee);
    // z2 = relu(bn2(relu(bn1(ee)) @ ze_W + ze_b))   [BN1+relu fused into A-load]
    tgemm<<<dim3(EE / 128, 1), 256, TG_SMEM>>>(ee, ze_W, EE, 128, 128,
                                               ze_bn1, ze_b, nullptr, ze_bn2, 1,
                                               nullptr, nullptr, z2);
    k_init_h<<<(NN * 32 + 255) / 256, 256>>>(x_node, node_emb, h);
    k_init_vn<<<(GG * DD + 255) / 256, 256>>>(vn_emb, vn);

    const int* srcp = edge_index;
    const int* dstp = edge_index + EE;
    const int nblk = (NN + 127) / 128;

    for (int l = 0; l < LL; l++) {
        k_hin_agg<<<(NN * 32 + 255) / 256, 256>>>(h, vn, batch, conv_eps + l, hin, agg);
        // edge_emb = z2 @ Wp + bp + edge_attr @ We + be
        tgemm<<<dim3(EE / 128, 1), 256, TG_SMEM>>>(z2, conv_Wp + (size_t)l * DD * DD,
                                                   EE, 128, 128,
                                                   nullptr, conv_bp + l * DD, conv_be + l * DD,
                                                   nullptr, 0,
                                                   edge_attr, conv_We + (size_t)l * 7 * DD, ee);
        k_scatter<<<(EE * 32 + 255) / 256, 256>>>(srcp, dstp, hin, ee, agg);
        // t2 = relu(bn(agg @ W1 + b1))
        tgemm<<<dim3(nblk, 2), 256, TG_SMEM>>>(agg, conv_W1 + (size_t)l * DD * 2 * DD,
                                               NN, DD, 2 * DD,
                                               nullptr, conv_b1 + l * 2 * DD, nullptr,
                                               conv_bn + (size_t)l * 4 * 2 * DD, 1,
                                               nullptr, nullptr, t2);
        // h = act(layer_bn(t2 @ W2 + b2))
        tgemm<<<dim3(nblk, 1), 256, TG_SMEM>>>(t2, conv_W2 + (size_t)l * 2 * DD * DD,
                                               NN, 2 * DD, DD,
                                               nullptr, conv_b2 + l * DD, nullptr,
                                               layer_bn + (size_t)l * 4 * DD,
                                               (l < LL - 1) ? 1 : 0,
                                               nullptr, nullptr, h);
        if (l < LL - 1) {
            k_vn_agg<<<GG, DD>>>(hin, batch, vn, vt);
            k_vn_mlp<<<GG, 256>>>(vt, vn_W1 + (size_t)l * DD * 2 * DD, vn_b1 + l * 2 * DD,
                                  vn_bn1 + (size_t)l * 4 * 2 * DD,
                                  vn_W2 + (size_t)l * 2 * DD * DD, vn_b2 + l * DD,
                                  vn_bn2 + (size_t)l * 4 * DD, vn);
        }
    }
}

// round 4
// speedup vs baseline: 2.5376x; 1.2952x over previous
#include <cuda_runtime.h>
#include <cuda_fp16.h>
#include <cstddef>
#include <cstdint>

#define NN 100000
#define EE 640000
#define PP 640000
#define DD 128
#define GG 128
#define LL 3
#define BN_EPS 1e-5f

// ---------------- device scratch ----------------
__device__ __half g_z2 [(size_t)EE * DD];     // fp16 z after encoder (storage only)
__device__ float  g_hin[(size_t)NN * DD];
__device__ float  g_agg[(size_t)NN * DD];
__device__ float  g_t2 [(size_t)NN * 2 * DD];
__device__ float  g_vn [GG * DD];
__device__ float  g_vt [GG * DD];

// ---------------- helpers ----------------
__device__ __forceinline__ void red_add_v4(float* p, float4 v) {
    asm volatile("red.global.add.v4.f32 [%0], {%1,%2,%3,%4};"
                 :: "l"(p), "f"(v.x), "f"(v.y), "f"(v.z), "f"(v.w) : "memory");
}
__device__ __forceinline__ unsigned f2tf(float f) {
    unsigned u;
    asm("cvt.rna.tf32.f32 %0, %1;" : "=r"(u) : "f"(f));
    return u;
}
__device__ __forceinline__ void mma_tf32(float* c, const unsigned* a, const unsigned* b) {
    asm volatile("mma.sync.aligned.m16n8k8.row.col.f32.tf32.tf32.f32 "
                 "{%0,%1,%2,%3}, {%4,%5,%6,%7}, {%8,%9}, {%0,%1,%2,%3};"
                 : "+f"(c[0]), "+f"(c[1]), "+f"(c[2]), "+f"(c[3])
                 : "r"(a[0]), "r"(a[1]), "r"(a[2]), "r"(a[3]),
                   "r"(b[0]), "r"(b[1]));
}
__device__ __forceinline__ unsigned pack2h(float x, float y) {
    __half2 h = __floats2half2_rn(x, y);
    return *(unsigned*)&h;
}

#define AS_S 68
#define BS_S 132
#define TG_SMEM ((128 * AS_S + 64 * BS_S) * 4)   // 68608 B

// proven round-2 mma inner loop over a 64-wide k chunk
#define MMA_CHUNK(As, Bs, warp_m, warp_n, g, t, acc)                               \
    _Pragma("unroll")                                                              \
    for (int kk = 0; kk < 64; kk += 8) {                                           \
        unsigned af[4][4], bf[4][2];                                               \
        _Pragma("unroll")                                                          \
        for (int mt = 0; mt < 4; mt++) {                                           \
            int mb = (warp_m) * 64 + mt * 16;                                      \
            af[mt][0] = (As)[(mb + (g)) * AS_S + kk + (t)];                        \
            af[mt][1] = (As)[(mb + (g) + 8) * AS_S + kk + (t)];                    \
            af[mt][2] = (As)[(mb + (g)) * AS_S + kk + (t) + 4];                    \
            af[mt][3] = (As)[(mb + (g) + 8) * AS_S + kk + (t) + 4];                \
        }                                                                          \
        _Pragma("unroll")                                                          \
        for (int nt = 0; nt < 4; nt++) {                                           \
            int n = (warp_n) * 32 + nt * 8 + (g);                                  \
            bf[nt][0] = (Bs)[(kk + (t)) * BS_S + n];                               \
            bf[nt][1] = (Bs)[(kk + (t) + 4) * BS_S + n];                           \
        }                                                                          \
        _Pragma("unroll")                                                          \
        for (int mt = 0; mt < 4; mt++)                                             \
            _Pragma("unroll")                                                      \
            for (int nt = 0; nt < 4; nt++)                                         \
                mma_tf32(acc[mt][nt], af[mt], bf[nt]);                             \
    }

// ---------------- small utility kernels ----------------
__global__ void k_init_h(const int* __restrict__ xn, const float* __restrict__ emb,
                         float* __restrict__ h) {
    int i = blockIdx.x * blockDim.x + threadIdx.x;
    if (i >= NN * 32) return;
    int row = i >> 5, q = (i & 31) << 2;
    float4 v = *(const float4*)(emb + (size_t)xn[row] * DD + q);
    *(float4*)(h + (size_t)row * DD + q) = v;
}

__global__ void k_init_vn(const float* __restrict__ emb, float* __restrict__ vn) {
    int i = blockIdx.x * blockDim.x + threadIdx.x;
    if (i < GG * DD) vn[i] = emb[i & (DD - 1)];
}

// hin = h + vn[batch];  agg = (1+eps)*hin
__global__ void k_hin_agg(const float* __restrict__ h, const float* __restrict__ vn,
                          const int* __restrict__ batch, const float* __restrict__ epsp,
                          float* __restrict__ hin, float* __restrict__ agg) {
    int i = blockIdx.x * blockDim.x + threadIdx.x;
    if (i >= NN * 32) return;
    int row = i >> 5, q = (i & 31) << 2;
    int g = __ldg(batch + row);
    float c = 1.0f + __ldg(epsp);
    float4 a = *(const float4*)(h + (size_t)row * DD + q);
    float4 b = *(const float4*)(vn + (size_t)g * DD + q);
    a.x += b.x; a.y += b.y; a.z += b.z; a.w += b.w;
    *(float4*)(hin + (size_t)row * DD + q) = a;
    float4 e = make_float4(c * a.x, c * a.y, c * a.z, c * a.w);
    *(float4*)(agg + (size_t)row * DD + q) = e;
}

// ---------------- fused z-encoder (tf32 core) ----------------
// z2[e] = fp16( relu(bn2( relu(bn1(segment_sum)) @ ze_W + ze_b )) )
__global__ __launch_bounds__(256, 2)
void k_zenc(const int* __restrict__ pidx, const float* __restrict__ penc,
            const int* __restrict__ pbatch, const float* __restrict__ zinit,
            const float* __restrict__ bn1, const float* __restrict__ zeb,
            const float* __restrict__ bn2, const float* __restrict__ zeW,
            __half* __restrict__ z2) {
    extern __shared__ unsigned smem[];
    unsigned* As = smem;
    unsigned* Bs = smem + 128 * AS_S;
    __shared__ int starts[129];
    __shared__ float sc1[128], sh1[128];

    const int tid = threadIdx.x;
    const int row0 = blockIdx.x * 128;
    if (tid < 129) {
        int target = row0 + tid;
        int lo = 0, hi = PP;
        while (lo < hi) { int m = (lo + hi) >> 1; if (pbatch[m] < target) lo = m + 1; else hi = m; }
        starts[tid] = lo;
    }
    if (tid < 128) {
        float s = bn1[tid] * rsqrtf(bn1[3 * 128 + tid] + BN_EPS);
        sc1[tid] = s;
        sh1[tid] = bn1[128 + tid] - bn1[2 * 128 + tid] * s;
    }
    __syncthreads();

    const int lane = tid & 31, wid = tid >> 5;
    const int g = lane >> 2, t = lane & 3;
    const int warp_m = wid & 1, warp_n = wid >> 1;
    const int brow = tid >> 5, bcol = (tid & 31) << 2;
    const int ar = tid >> 1;                 // row 0..127 (2 threads per row)

    float acc[4][4][4];
#pragma unroll
    for (int mt = 0; mt < 4; mt++)
#pragma unroll
        for (int nt = 0; nt < 4; nt++)
#pragma unroll
            for (int q = 0; q < 4; q++) acc[mt][nt][q] = 0.f;

    const int st = starts[ar], en = starts[ar + 1];

    for (int k0 = 0; k0 < 128; k0 += 64) {
        __syncthreads();
        // B chunk 64x128
#pragma unroll
        for (int p = 0; p < 8; p++) {
            int r = brow + p * 8;
            float4 v = *(const float4*)(zeW + (size_t)(k0 + r) * 128 + bcol);
            unsigned* d = Bs + r * BS_S + bcol;
            d[0] = f2tf(v.x); d[1] = f2tf(v.y); d[2] = f2tf(v.z); d[3] = f2tf(v.w);
        }
        // A chunk 128x64 via segment sum, two 16-col sub-passes per thread
#pragma unroll
        for (int sub = 0; sub < 2; sub++) {
            int cc = (tid & 1) * 32 + sub * 16;    // local col in chunk
            float4 a[4];
#pragma unroll
            for (int j = 0; j < 4; j++) a[j] = make_float4(0.f, 0.f, 0.f, 0.f);
            for (int p = st; p < en; p++) {
                int zi = __ldg(pidx + p);
                float w = __ldg(penc + p);
                const float* zr = zinit + (size_t)zi * 128 + k0 + cc;
#pragma unroll
                for (int j = 0; j < 4; j++) {
                    float4 v = *(const float4*)(zr + 4 * j);
                    a[j].x += v.x * w; a[j].y += v.y * w; a[j].z += v.z * w; a[j].w += v.w * w;
                }
            }
#pragma unroll
            for (int j = 0; j < 4; j++) {
                int c = cc + 4 * j;
                int gc = k0 + c;
                float y0 = fmaxf(a[j].x * sc1[gc + 0] + sh1[gc + 0], 0.f);
                float y1 = fmaxf(a[j].y * sc1[gc + 1] + sh1[gc + 1], 0.f);
                float y2 = fmaxf(a[j].z * sc1[gc + 2] + sh1[gc + 2], 0.f);
                float y3 = fmaxf(a[j].w * sc1[gc + 3] + sh1[gc + 3], 0.f);
                unsigned* d = As + ar * AS_S + c;
                d[0] = f2tf(y0); d[1] = f2tf(y1); d[2] = f2tf(y2); d[3] = f2tf(y3);
            }
        }
        __syncthreads();
        MMA_CHUNK(As, Bs, warp_m, warp_n, g, t, acc)
    }

    // epilogue: bn2 + bias + relu -> fp16
    float sc[8], sh[8];
#pragma unroll
    for (int nt = 0; nt < 4; nt++)
#pragma unroll
        for (int hh = 0; hh < 2; hh++) {
            int c = warp_n * 32 + nt * 8 + 2 * t + hh;
            float s = bn2[c] * rsqrtf(bn2[3 * 128 + c] + BN_EPS);
            sc[nt * 2 + hh] = s;
            sh[nt * 2 + hh] = bn2[128 + c] + (zeb[c] - bn2[2 * 128 + c]) * s;
        }
#pragma unroll
    for (int mt = 0; mt < 4; mt++)
#pragma unroll
        for (int half = 0; half < 2; half++) {
            int gr = row0 + warp_m * 64 + mt * 16 + g + 8 * half;
#pragma unroll
            for (int nt = 0; nt < 4; nt++) {
                float y0 = fmaxf(acc[mt][nt][half * 2 + 0] * sc[nt * 2 + 0] + sh[nt * 2 + 0], 0.f);
                float y1 = fmaxf(acc[mt][nt][half * 2 + 1] * sc[nt * 2 + 1] + sh[nt * 2 + 1], 0.f);
                int cb = warp_n * 32 + nt * 8 + 2 * t;
                *(unsigned*)(z2 + (size_t)gr * 128 + cb) = pack2h(y0, y1);
            }
        }
}

// ---------------- fused edge GEMM + gather + scatter (tf32 core) ----------------
// ee = z2@Wp + bp + be + edge_attr@We (smem only); agg[dst] += relu(hin[src] + ee)
__global__ __launch_bounds__(256, 2)
void k_edge_fused(const __half* __restrict__ z2, const float* __restrict__ Wp,
                  const float* __restrict__ bp, const float* __restrict__ be,
                  const float* __restrict__ Ae, const float* __restrict__ We7,
                  const int* __restrict__ src, const int* __restrict__ dst,
                  const float* __restrict__ hin, float* __restrict__ agg) {
    extern __shared__ unsigned smem[];
    unsigned* As = smem;
    unsigned* Bs = smem + 128 * AS_S;
    float* eeS = (float*)smem;              // [128][132] floats, aliases As/Bs
    __shared__ float AeS[128 * 8];
    __shared__ float WeS[7 * 128];

    const int tid = threadIdx.x;
    const int row0 = blockIdx.x * 128;

    for (int i = tid; i < 128 * 7; i += 256) {
        int r = i / 7, c = i % 7;
        AeS[r * 8 + c] = Ae[(size_t)(row0 + r) * 7 + c];
    }
    for (int i = tid; i < 7 * 128; i += 256) WeS[i] = We7[i];

    const int lane = tid & 31, wid = tid >> 5;
    const int g = lane >> 2, t = lane & 3;
    const int warp_m = wid & 1, warp_n = wid >> 1;
    const int arow = tid >> 4, acol = (tid & 15) << 2;
    const int brow = tid >> 5, bcol = (tid & 31) << 2;

    float acc[4][4][4];
#pragma unroll
    for (int mt = 0; mt < 4; mt++)
#pragma unroll
        for (int nt = 0; nt < 4; nt++)
#pragma unroll
            for (int q = 0; q < 4; q++) acc[mt][nt][q] = 0.f;

    for (int k0 = 0; k0 < 128; k0 += 64) {
        __syncthreads();
#pragma unroll
        for (int p = 0; p < 8; p++) {
            int r = arow + p * 16;
            const __half2* zp = (const __half2*)(z2 + (size_t)(row0 + r) * 128 + k0 + acol);
            float2 f01 = __half22float2(zp[0]);
            float2 f23 = __half22float2(zp[1]);
            unsigned* d = As + r * AS_S + acol;
            d[0] = f2tf(f01.x); d[1] = f2tf(f01.y); d[2] = f2tf(f23.x); d[3] = f2tf(f23.y);
        }
#pragma unroll
        for (int p = 0; p < 8; p++) {
            int r = brow + p * 8;
            float4 v = *(const float4*)(Wp + (size_t)(k0 + r) * 128 + bcol);
            unsigned* d = Bs + r * BS_S + bcol;
            d[0] = f2tf(v.x); d[1] = f2tf(v.y); d[2] = f2tf(v.z); d[3] = f2tf(v.w);
        }
        __syncthreads();
        MMA_CHUNK(As, Bs, warp_m, warp_n, g, t, acc)
    }
    __syncthreads();   // done reading As/Bs before aliasing as eeS

    float bsum[8];
#pragma unroll
    for (int nt = 0; nt < 4; nt++)
#pragma unroll
        for (int hh = 0; hh < 2; hh++) {
            int c = warp_n * 32 + nt * 8 + 2 * t + hh;
            bsum[nt * 2 + hh] = bp[c] + be[c];
        }
#pragma unroll
    for (int mt = 0; mt < 4; mt++)
#pragma unroll
        for (int half = 0; half < 2; half++) {
            int lr = warp_m * 64 + mt * 16 + g + 8 * half;
            float a7[7];
#pragma unroll
            for (int k = 0; k < 7; k++) a7[k] = AeS[lr * 8 + k];
#pragma unroll
            for (int nt = 0; nt < 4; nt++) {
                int cb = warp_n * 32 + nt * 8 + 2 * t;
                float y0 = acc[mt][nt][half * 2 + 0] + bsum[nt * 2 + 0];
                float y1 = acc[mt][nt][half * 2 + 1] + bsum[nt * 2 + 1];
#pragma unroll
                for (int k = 0; k < 7; k++) {
                    y0 = fmaf(a7[k], WeS[k * 128 + cb], y0);
                    y1 = fmaf(a7[k], WeS[k * 128 + cb + 1], y1);
                }
                *(float2*)(eeS + lr * 132 + cb) = make_float2(y0, y1);
            }
        }
    __syncthreads();

    // gather + relu + scatter: warp per edge
#pragma unroll 4
    for (int i = 0; i < 16; i++) {
        int lr = wid * 16 + i;
        int e = row0 + lr;
        int s = __ldg(src + e), d = __ldg(dst + e);
        float4 ev = *(float4*)(eeS + lr * 132 + lane * 4);
        float4 hv = *(const float4*)(hin + (size_t)s * 128 + lane * 4);
        float4 m;
        m.x = fmaxf(hv.x + ev.x, 0.f);
        m.y = fmaxf(hv.y + ev.y, 0.f);
        m.z = fmaxf(hv.z + ev.z, 0.f);
        m.w = fmaxf(hv.w + ev.w, 0.f);
        red_add_v4(agg + (size_t)d * 128 + lane * 4, m);
    }
}

// ---------------- node GEMM (round-2 verbatim core): C = act(bn(A@B + bias)) ----------------
__global__ __launch_bounds__(256, 2)
void tgemm(const float* __restrict__ A, const float* __restrict__ B,
           int M, int K, int Nc,
           const float* __restrict__ bias, const float* __restrict__ bn,
           int relu, float* __restrict__ C) {
    extern __shared__ unsigned smem[];
    unsigned* As = smem;
    unsigned* Bs = smem + 128 * AS_S;
    const int tid = threadIdx.x;
    const int lane = tid & 31, wid = tid >> 5;
    const int g = lane >> 2, t = lane & 3;
    const int warp_m = wid & 1, warp_n = wid >> 1;
    const int row0 = blockIdx.x * 128;
    const int col0 = blockIdx.y * 128;
    const int arow = tid >> 4, acol = (tid & 15) << 2;
    const int brow = tid >> 5, bcol = (tid & 31) << 2;

    float acc[4][4][4];
#pragma unroll
    for (int mt = 0; mt < 4; mt++)
#pragma unroll
        for (int nt = 0; nt < 4; nt++)
#pragma unroll
            for (int q = 0; q < 4; q++) acc[mt][nt][q] = 0.f;

    for (int k0 = 0; k0 < K; k0 += 64) {
        __syncthreads();
#pragma unroll
        for (int p = 0; p < 8; p++) {
            int r = arow + p * 16;
            int gr = row0 + r;
            float4 v = make_float4(0.f, 0.f, 0.f, 0.f);
            if (gr < M) v = *(const float4*)(A + (size_t)gr * K + k0 + acol);
            unsigned* d = As + r * AS_S + acol;
            d[0] = f2tf(v.x); d[1] = f2tf(v.y); d[2] = f2tf(v.z); d[3] = f2tf(v.w);
        }
#pragma unroll
        for (int p = 0; p < 8; p++) {
            int r = brow + p * 8;
            float4 v = *(const float4*)(B + (size_t)(k0 + r) * Nc + col0 + bcol);
            unsigned* d = Bs + r * BS_S + bcol;
            d[0] = f2tf(v.x); d[1] = f2tf(v.y); d[2] = f2tf(v.z); d[3] = f2tf(v.w);
        }
        __syncthreads();
        MMA_CHUNK(As, Bs, warp_m, warp_n, g, t, acc)
    }

    float sc[8], sh[8];
#pragma unroll
    for (int nt = 0; nt < 4; nt++)
#pragma unroll
        for (int hh = 0; hh < 2; hh++) {
            int c = col0 + warp_n * 32 + nt * 8 + 2 * t + hh;
            float s = bn[c] * rsqrtf(bn[3 * Nc + c] + BN_EPS);
            sc[nt * 2 + hh] = s;
            sh[nt * 2 + hh] = bn[Nc + c] + (bias[c] - bn[2 * Nc + c]) * s;
        }
#pragma unroll
    for (int mt = 0; mt < 4; mt++)
#pragma unroll
        for (int half = 0; half < 2; half++) {
            int gr = row0 + warp_m * 64 + mt * 16 + g + 8 * half;
            if (gr >= M) continue;
#pragma unroll
            for (int nt = 0; nt < 4; nt++) {
                float y0 = acc[mt][nt][half * 2 + 0] * sc[nt * 2 + 0] + sh[nt * 2 + 0];
                float y1 = acc[mt][nt][half * 2 + 1] * sc[nt * 2 + 1] + sh[nt * 2 + 1];
                if (relu) { y0 = fmaxf(y0, 0.f); y1 = fmaxf(y1, 0.f); }
                int cb = warp_n * 32 + nt * 8 + 2 * t;
                *(float2*)(C + (size_t)gr * Nc + col0 + cb) = make_float2(y0, y1);
            }
        }
}

// ---------------- virtual node ----------------
__global__ void k_vn_agg(const float* __restrict__ hin, const int* __restrict__ batch,
                         const float* __restrict__ vn, float* __restrict__ vt) {
    int g = blockIdx.x, c = threadIdx.x;
    int lo = 0, hi = NN;
    while (lo < hi) { int m = (lo + hi) >> 1; if (batch[m] < g) lo = m + 1; else hi = m; }
    int start = lo;
    lo = start; hi = NN;
    while (lo < hi) { int m = (lo + hi) >> 1; if (batch[m] < g + 1) lo = m + 1; else hi = m; }
    int end = lo;
    float sum = 0.f;
    for (int i = start; i < end; i++) sum += hin[(size_t)i * DD + c];
    vt[g * DD + c] = sum + vn[g * DD + c];
}

__global__ void k_vn_mlp(const float* __restrict__ vt,
                         const float* __restrict__ W1, const float* __restrict__ b1,
                         const float* __restrict__ bn1,
                         const float* __restrict__ W2, const float* __restrict__ b2,
                         const float* __restrict__ bn2, float* __restrict__ vn) {
    __shared__ float xr[DD];
    __shared__ float tr[2 * DD];
    int g = blockIdx.x, tid = threadIdx.x;
    if (tid < DD) xr[tid] = vt[g * DD + tid];
    __syncthreads();
    float acc = b1[tid];
#pragma unroll 8
    for (int k = 0; k < DD; k++) acc = fmaf(xr[k], W1[(size_t)k * 2 * DD + tid], acc);
    float s = bn1[tid] * rsqrtf(bn1[3 * 2 * DD + tid] + BN_EPS);
    acc = (acc - bn1[2 * 2 * DD + tid]) * s + bn1[2 * DD + tid];
    tr[tid] = fmaxf(acc, 0.f);
    __syncthreads();
    if (tid < DD) {
        float a2 = b2[tid];
#pragma unroll 8
        for (int k = 0; k < 2 * DD; k++) a2 = fmaf(tr[k], W2[(size_t)k * DD + tid], a2);
        float s2 = bn2[tid] * rsqrtf(bn2[3 * DD + tid] + BN_EPS);
        a2 = (a2 - bn2[2 * DD + tid]) * s2 + bn2[DD + tid];
        vn[g * DD + tid] = fmaxf(a2, 0.f);
    }
}

// ---------------- host launcher ----------------
extern "C" void kernel_launch(void* const* d_in, const int* in_sizes, int n_in,
                              void* d_out, int out_size) {
    const int*   x_node     = (const int*)d_in[0];
    const int*   edge_index = (const int*)d_in[1];
    const float* edge_attr  = (const float*)d_in[2];
    const int*   batch      = (const int*)d_in[3];
    const int*   pos_index  = (const int*)d_in[4];
    const float* pos_enc    = (const float*)d_in[5];
    const int*   pos_batch  = (const int*)d_in[6];
    const float* node_emb   = (const float*)d_in[7];
    const float* z_init     = (const float*)d_in[8];
    const float* ze_bn1     = (const float*)d_in[9];
    const float* ze_W       = (const float*)d_in[10];
    const float* ze_b       = (const float*)d_in[11];
    const float* ze_bn2     = (const float*)d_in[12];
    const float* vn_emb     = (const float*)d_in[13];
    const float* conv_We    = (const float*)d_in[14];
    const float* conv_be    = (const float*)d_in[15];
    const float* conv_Wp    = (const float*)d_in[16];
    const float* conv_bp    = (const float*)d_in[17];
    const float* conv_W1    = (const float*)d_in[18];
    const float* conv_b1    = (const float*)d_in[19];
    const float* conv_bn    = (const float*)d_in[20];
    const float* conv_W2    = (const float*)d_in[21];
    const float* conv_b2    = (const float*)d_in[22];
    const float* conv_eps   = (const float*)d_in[23];
    const float* layer_bn   = (const float*)d_in[24];
    const float* vn_W1      = (const float*)d_in[25];
    const float* vn_b1      = (const float*)d_in[26];
    const float* vn_bn1     = (const float*)d_in[27];
    const float* vn_W2      = (const float*)d_in[28];
    const float* vn_b2      = (const float*)d_in[29];
    const float* vn_bn2     = (const float*)d_in[30];

    __half* z2;
    float *hin, *agg, *t2, *vn, *vt;
    cudaGetSymbolAddress((void**)&z2,  g_z2);
    cudaGetSymbolAddress((void**)&hin, g_hin);
    cudaGetSymbolAddress((void**)&agg, g_agg);
    cudaGetSymbolAddress((void**)&t2,  g_t2);
    cudaGetSymbolAddress((void**)&vn,  g_vn);
    cudaGetSymbolAddress((void**)&vt,  g_vt);

    cudaFuncSetAttribute(k_zenc, cudaFuncAttributeMaxDynamicSharedMemorySize, TG_SMEM);
    cudaFuncSetAttribute(k_edge_fused, cudaFuncAttributeMaxDynamicSharedMemorySize, TG_SMEM);
    cudaFuncSetAttribute(tgemm, cudaFuncAttributeMaxDynamicSharedMemorySize, TG_SMEM);

    float* h = (float*)d_out;

    k_zenc<<<EE / 128, 256, TG_SMEM>>>(pos_index, pos_enc, pos_batch, z_init,
                                       ze_bn1, ze_b, ze_bn2, ze_W, z2);
    k_init_h<<<(NN * 32 + 255) / 256, 256>>>(x_node, node_emb, h);
    k_init_vn<<<(GG * DD + 255) / 256, 256>>>(vn_emb, vn);

    const int* srcp = edge_index;
    const int* dstp = edge_index + EE;
    const int nblk = (NN + 127) / 128;

    for (int l = 0; l < LL; l++) {
        k_hin_agg<<<(NN * 32 + 255) / 256, 256>>>(h, vn, batch, conv_eps + l, hin, agg);
        k_edge_fused<<<EE / 128, 256, TG_SMEM>>>(z2, conv_Wp + (size_t)l * DD * DD,
                                                 conv_bp + l * DD, conv_be + l * DD,
                                                 edge_attr, conv_We + (size_t)l * 7 * DD,
                                                 srcp, dstp, hin, agg);
        tgemm<<<dim3(nblk, 2), 256, TG_SMEM>>>(agg, conv_W1 + (size_t)l * DD * 2 * DD,
                                               NN, DD, 2 * DD,
                                               conv_b1 + l * 2 * DD,
                                               conv_bn + (size_t)l * 4 * 2 * DD, 1, t2);
        tgemm<<<dim3(nblk, 1), 256, TG_SMEM>>>(t2, conv_W2 + (size_t)l * 2 * DD * DD,
                                               NN, 2 * DD, DD,
                                               conv_b2 + l * DD,
                                               layer_bn + (size_t)l * 4 * DD,
                                               (l < LL - 1) ? 1 : 0, h);
        if (l < LL - 1) {
            k_vn_agg<<<GG, DD>>>(hin, batch, vn, vt);
            k_vn_mlp<<<GG, 256>>>(vt, vn_W1 + (size_t)l * DD * 2 * DD, vn_b1 + l * 2 * DD,
                                  vn_bn1 + (size_t)l * 4 * 2 * DD,
                                  vn_W2 + (size_t)l * 2 * DD * DD, vn_b2 + l * DD,
                                  vn_bn2 + (size_t)l * 4 * DD, vn);
        }
    }
}

// round 6
// speedup vs baseline: 2.6297x; 1.0363x over previous
#include <cuda_runtime.h>
#include <cuda_fp16.h>
#include <cstddef>
#include <cstdint>

#define NN 100000
#define EE 640000
#define PP 640000
#define DD 128
#define GG 128
#define LL 3
#define BN_EPS 1e-5f

// ---------------- device scratch ----------------
__device__ __half g_z2 [(size_t)EE * DD];     // fp16 z after encoder (storage only)
__device__ float  g_hin[(size_t)NN * DD];     // fp32 h_in (round-4 precision)
__device__ float  g_agg[(size_t)NN * DD];     // fp32 (atomic target)
__device__ float  g_t2 [(size_t)NN * 2 * DD]; // fp32 MLP hidden (round-4 precision)
__device__ float  g_vn [GG * DD];
__device__ float  g_vt [GG * DD];

// ---------------- helpers ----------------
__device__ __forceinline__ void red_add_v4(float* p, float4 v) {
    asm volatile("red.global.add.v4.f32 [%0], {%1,%2,%3,%4};"
                 :: "l"(p), "f"(v.x), "f"(v.y), "f"(v.z), "f"(v.w) : "memory");
}
__device__ __forceinline__ unsigned f2tf(float f) {
    unsigned u;
    asm("cvt.rna.tf32.f32 %0, %1;" : "=r"(u) : "f"(f));
    return u;
}
__device__ __forceinline__ void mma_tf32(float* c, const unsigned* a, const unsigned* b) {
    asm volatile("mma.sync.aligned.m16n8k8.row.col.f32.tf32.tf32.f32 "
                 "{%0,%1,%2,%3}, {%4,%5,%6,%7}, {%8,%9}, {%0,%1,%2,%3};"
                 : "+f"(c[0]), "+f"(c[1]), "+f"(c[2]), "+f"(c[3])
                 : "r"(a[0]), "r"(a[1]), "r"(a[2]), "r"(a[3]),
                   "r"(b[0]), "r"(b[1]));
}
__device__ __forceinline__ unsigned pack2h(float x, float y) {
    __half2 h = __floats2half2_rn(x, y);
    return *(unsigned*)&h;
}

#define AS_S 68
#define BS_S 132
#define TG_SMEM ((128 * AS_S + 64 * BS_S) * 4)   // 68608 B

// proven tf32 mma inner loop over a 64-wide k chunk
#define MMA_CHUNK(As, Bs, warp_m, warp_n, g, t, acc)                               \
    _Pragma("unroll")                                                              \
    for (int kk = 0; kk < 64; kk += 8) {                                           \
        unsigned af[4][4], bf[4][2];                                               \
        _Pragma("unroll")                                                          \
        for (int mt = 0; mt < 4; mt++) {                                           \
            int mb = (warp_m) * 64 + mt * 16;                                      \
            af[mt][0] = (As)[(mb + (g)) * AS_S + kk + (t)];                        \
            af[mt][1] = (As)[(mb + (g) + 8) * AS_S + kk + (t)];                    \
            af[mt][2] = (As)[(mb + (g)) * AS_S + kk + (t) + 4];                    \
            af[mt][3] = (As)[(mb + (g) + 8) * AS_S + kk + (t) + 4];                \
        }                                                                          \
        _Pragma("unroll")                                                          \
        for (int nt = 0; nt < 4; nt++) {                                           \
            int n = (warp_n) * 32 + nt * 8 + (g);                                  \
            bf[nt][0] = (Bs)[(kk + (t)) * BS_S + n];                               \
            bf[nt][1] = (Bs)[(kk + (t) + 4) * BS_S + n];                           \
        }                                                                          \
        _Pragma("unroll")                                                          \
        for (int mt = 0; mt < 4; mt++)                                             \
            _Pragma("unroll")                                                      \
            for (int nt = 0; nt < 4; nt++)                                         \
                mma_tf32(acc[mt][nt], af[mt], bf[nt]);                             \
    }

// ---------------- init kernels ----------------
__global__ void k_init_vn(const float* __restrict__ emb, float* __restrict__ vn) {
    int i = blockIdx.x * blockDim.x + threadIdx.x;
    if (i < GG * DD) vn[i] = emb[i & (DD - 1)];
}

// hin0 = node_emb[xn] + vn_emb; agg0 = (1+eps0)*hin0   (all fp32)
__global__ void k_init_hin(const int* __restrict__ xn, const float* __restrict__ emb,
                           const float* __restrict__ vne, const float* __restrict__ epsp,
                           float* __restrict__ hin, float* __restrict__ agg) {
    int i = blockIdx.x * blockDim.x + threadIdx.x;
    if (i >= NN * 32) return;
    int row = i >> 5, q = (i & 31) << 2;
    float c = 1.0f + __ldg(epsp);
    float4 a = *(const float4*)(emb + (size_t)xn[row] * DD + q);
    float4 b = *(const float4*)(vne + q);
    a.x += b.x; a.y += b.y; a.z += b.z; a.w += b.w;
    *(float4*)(hin + (size_t)row * DD + q) = a;
    float4 e = make_float4(c * a.x, c * a.y, c * a.z, c * a.w);
    *(float4*)(agg + (size_t)row * DD + q) = e;
}

// ---------------- fused z-encoder (round-4 verbatim) ----------------
__global__ __launch_bounds__(256, 2)
void k_zenc(const int* __restrict__ pidx, const float* __restrict__ penc,
            const int* __restrict__ pbatch, const float* __restrict__ zinit,
            const float* __restrict__ bn1, const float* __restrict__ zeb,
            const float* __restrict__ bn2, const float* __restrict__ zeW,
            __half* __restrict__ z2) {
    extern __shared__ unsigned smem[];
    unsigned* As = smem;
    unsigned* Bs = smem + 128 * AS_S;
    __shared__ int starts[129];
    __shared__ float sc1[128], sh1[128];

    const int tid = threadIdx.x;
    const int row0 = blockIdx.x * 128;
    if (tid < 129) {
        int target = row0 + tid;
        int lo = 0, hi = PP;
        while (lo < hi) { int m = (lo + hi) >> 1; if (pbatch[m] < target) lo = m + 1; else hi = m; }
        starts[tid] = lo;
    }
    if (tid < 128) {
        float s = bn1[tid] * rsqrtf(bn1[3 * 128 + tid] + BN_EPS);
        sc1[tid] = s;
        sh1[tid] = bn1[128 + tid] - bn1[2 * 128 + tid] * s;
    }
    __syncthreads();

    const int lane = tid & 31, wid = tid >> 5;
    const int g = lane >> 2, t = lane & 3;
    const int warp_m = wid & 1, warp_n = wid >> 1;
    const int brow = tid >> 5, bcol = (tid & 31) << 2;
    const int ar = tid >> 1;

    float acc[4][4][4];
#pragma unroll
    for (int mt = 0; mt < 4; mt++)
#pragma unroll
        for (int nt = 0; nt < 4; nt++)
#pragma unroll
            for (int q = 0; q < 4; q++) acc[mt][nt][q] = 0.f;

    const int st = starts[ar], en = starts[ar + 1];

    for (int k0 = 0; k0 < 128; k0 += 64) {
        __syncthreads();
#pragma unroll
        for (int p = 0; p < 8; p++) {
            int r = brow + p * 8;
            float4 v = *(const float4*)(zeW + (size_t)(k0 + r) * 128 + bcol);
            unsigned* d = Bs + r * BS_S + bcol;
            d[0] = f2tf(v.x); d[1] = f2tf(v.y); d[2] = f2tf(v.z); d[3] = f2tf(v.w);
        }
#pragma unroll
        for (int sub = 0; sub < 2; sub++) {
            int cc = (tid & 1) * 32 + sub * 16;
            float4 a[4];
#pragma unroll
            for (int j = 0; j < 4; j++) a[j] = make_float4(0.f, 0.f, 0.f, 0.f);
            for (int p = st; p < en; p++) {
                int zi = __ldg(pidx + p);
                float w = __ldg(penc + p);
                const float* zr = zinit + (size_t)zi * 128 + k0 + cc;
#pragma unroll
                for (int j = 0; j < 4; j++) {
                    float4 v = *(const float4*)(zr + 4 * j);
                    a[j].x += v.x * w; a[j].y += v.y * w; a[j].z += v.z * w; a[j].w += v.w * w;
                }
            }
#pragma unroll
            for (int j = 0; j < 4; j++) {
                int c = cc + 4 * j;
                int gc = k0 + c;
                float y0 = fmaxf(a[j].x * sc1[gc + 0] + sh1[gc + 0], 0.f);
                float y1 = fmaxf(a[j].y * sc1[gc + 1] + sh1[gc + 1], 0.f);
                float y2 = fmaxf(a[j].z * sc1[gc + 2] + sh1[gc + 2], 0.f);
                float y3 = fmaxf(a[j].w * sc1[gc + 3] + sh1[gc + 3], 0.f);
                unsigned* d = As + ar * AS_S + c;
                d[0] = f2tf(y0); d[1] = f2tf(y1); d[2] = f2tf(y2); d[3] = f2tf(y3);
            }
        }
        __syncthreads();
        MMA_CHUNK(As, Bs, warp_m, warp_n, g, t, acc)
    }

    float sc[8], sh[8];
#pragma unroll
    for (int nt = 0; nt < 4; nt++)
#pragma unroll
        for (int hh = 0; hh < 2; hh++) {
            int c = warp_n * 32 + nt * 8 + 2 * t + hh;
            float s = bn2[c] * rsqrtf(bn2[3 * 128 + c] + BN_EPS);
            sc[nt * 2 + hh] = s;
            sh[nt * 2 + hh] = bn2[128 + c] + (zeb[c] - bn2[2 * 128 + c]) * s;
        }
#pragma unroll
    for (int mt = 0; mt < 4; mt++)
#pragma unroll
        for (int half = 0; half < 2; half++) {
            int gr = row0 + warp_m * 64 + mt * 16 + g + 8 * half;
#pragma unroll
            for (int nt = 0; nt < 4; nt++) {
                float y0 = fmaxf(acc[mt][nt][half * 2 + 0] * sc[nt * 2 + 0] + sh[nt * 2 + 0], 0.f);
                float y1 = fmaxf(acc[mt][nt][half * 2 + 1] * sc[nt * 2 + 1] + sh[nt * 2 + 1], 0.f);
                int cb = warp_n * 32 + nt * 8 + 2 * t;
                *(unsigned*)(z2 + (size_t)gr * 128 + cb) = pack2h(y0, y1);
            }
        }
}

// ---------------- fused edge GEMM + gather + scatter (round-4 verbatim, fp32 hin) ----------------
__global__ __launch_bounds__(256, 2)
void k_edge_fused(const __half* __restrict__ z2, const float* __restrict__ Wp,
                  const float* __restrict__ bp, const float* __restrict__ be,
                  const float* __restrict__ Ae, const float* __restrict__ We7,
                  const int* __restrict__ src, const int* __restrict__ dst,
                  const float* __restrict__ hin, float* __restrict__ agg) {
    extern __shared__ unsigned smem[];
    unsigned* As = smem;
    unsigned* Bs = smem + 128 * AS_S;
    float* eeS = (float*)smem;              // [128][132], aliases As/Bs
    __shared__ float AeS[128 * 8];
    __shared__ float WeS[7 * 128];

    const int tid = threadIdx.x;
    const int row0 = blockIdx.x * 128;

    for (int i = tid; i < 128 * 7; i += 256) {
        int r = i / 7, c = i % 7;
        AeS[r * 8 + c] = Ae[(size_t)(row0 + r) * 7 + c];
    }
    for (int i = tid; i < 7 * 128; i += 256) WeS[i] = We7[i];

    const int lane = tid & 31, wid = tid >> 5;
    const int g = lane >> 2, t = lane & 3;
    const int warp_m = wid & 1, warp_n = wid >> 1;
    const int arow = tid >> 4, acol = (tid & 15) << 2;
    const int brow = tid >> 5, bcol = (tid & 31) << 2;

    float acc[4][4][4];
#pragma unroll
    for (int mt = 0; mt < 4; mt++)
#pragma unroll
        for (int nt = 0; nt < 4; nt++)
#pragma unroll
            for (int q = 0; q < 4; q++) acc[mt][nt][q] = 0.f;

    for (int k0 = 0; k0 < 128; k0 += 64) {
        __syncthreads();
#pragma unroll
        for (int p = 0; p < 8; p++) {
            int r = arow + p * 16;
            const __half2* zp = (const __half2*)(z2 + (size_t)(row0 + r) * 128 + k0 + acol);
            float2 f01 = __half22float2(zp[0]);
            float2 f23 = __half22float2(zp[1]);
            unsigned* d = As + r * AS_S + acol;
            d[0] = f2tf(f01.x); d[1] = f2tf(f01.y); d[2] = f2tf(f23.x); d[3] = f2tf(f23.y);
        }
#pragma unroll
        for (int p = 0; p < 8; p++) {
            int r = brow + p * 8;
            float4 v = *(const float4*)(Wp + (size_t)(k0 + r) * 128 + bcol);
            unsigned* d = Bs + r * BS_S + bcol;
            d[0] = f2tf(v.x); d[1] = f2tf(v.y); d[2] = f2tf(v.z); d[3] = f2tf(v.w);
        }
        __syncthreads();
        MMA_CHUNK(As, Bs, warp_m, warp_n, g, t, acc)
    }
    __syncthreads();

    float bsum[8];
#pragma unroll
    for (int nt = 0; nt < 4; nt++)
#pragma unroll
        for (int hh = 0; hh < 2; hh++) {
            int c = warp_n * 32 + nt * 8 + 2 * t + hh;
            bsum[nt * 2 + hh] = bp[c] + be[c];
        }
#pragma unroll
    for (int mt = 0; mt < 4; mt++)
#pragma unroll
        for (int half = 0; half < 2; half++) {
            int lr = warp_m * 64 + mt * 16 + g + 8 * half;
            float a7[7];
#pragma unroll
            for (int k = 0; k < 7; k++) a7[k] = AeS[lr * 8 + k];
#pragma unroll
            for (int nt = 0; nt < 4; nt++) {
                int cb = warp_n * 32 + nt * 8 + 2 * t;
                float y0 = acc[mt][nt][half * 2 + 0] + bsum[nt * 2 + 0];
                float y1 = acc[mt][nt][half * 2 + 1] + bsum[nt * 2 + 1];
#pragma unroll
                for (int k = 0; k < 7; k++) {
                    y0 = fmaf(a7[k], WeS[k * 128 + cb], y0);
                    y1 = fmaf(a7[k], WeS[k * 128 + cb + 1], y1);
                }
                *(float2*)(eeS + lr * 132 + cb) = make_float2(y0, y1);
            }
        }
    __syncthreads();

    // gather + relu + scatter: warp per edge
#pragma unroll 4
    for (int i = 0; i < 16; i++) {
        int lr = wid * 16 + i;
        int e = row0 + lr;
        int s = __ldg(src + e), d = __ldg(dst + e);
        float4 ev = *(float4*)(eeS + lr * 132 + lane * 4);
        float4 hv = *(const float4*)(hin + (size_t)s * 128 + lane * 4);
        float4 m;
        m.x = fmaxf(hv.x + ev.x, 0.f);
        m.y = fmaxf(hv.y + ev.y, 0.f);
        m.z = fmaxf(hv.z + ev.z, 0.f);
        m.w = fmaxf(hv.w + ev.w, 0.f);
        red_add_v4(agg + (size_t)d * 128 + lane * 4, m);
    }
}

// ---------------- W1 GEMM (round-4 tgemm verbatim): t2 = relu(bn(agg @ W1 + b1)) ----------------
__global__ __launch_bounds__(256, 2)
void tgemm(const float* __restrict__ A, const float* __restrict__ B,
           int M, int K, int Nc,
           const float* __restrict__ bias, const float* __restrict__ bn,
           int relu, float* __restrict__ C) {
    extern __shared__ unsigned smem[];
    unsigned* As = smem;
    unsigned* Bs = smem + 128 * AS_S;
    const int tid = threadIdx.x;
    const int lane = tid & 31, wid = tid >> 5;
    const int g = lane >> 2, t = lane & 3;
    const int warp_m = wid & 1, warp_n = wid >> 1;
    const int row0 = blockIdx.x * 128;
    const int col0 = blockIdx.y * 128;
    const int arow = tid >> 4, acol = (tid & 15) << 2;
    const int brow = tid >> 5, bcol = (tid & 31) << 2;

    float acc[4][4][4];
#pragma unroll
    for (int mt = 0; mt < 4; mt++)
#pragma unroll
        for (int nt = 0; nt < 4; nt++)
#pragma unroll
            for (int q = 0; q < 4; q++) acc[mt][nt][q] = 0.f;

    for (int k0 = 0; k0 < K; k0 += 64) {
        __syncthreads();
#pragma unroll
        for (int p = 0; p < 8; p++) {
            int r = arow + p * 16;
            int gr = row0 + r;
            float4 v = make_float4(0.f, 0.f, 0.f, 0.f);
            if (gr < M) v = *(const float4*)(A + (size_t)gr * K + k0 + acol);
            unsigned* d = As + r * AS_S + acol;
            d[0] = f2tf(v.x); d[1] = f2tf(v.y); d[2] = f2tf(v.z); d[3] = f2tf(v.w);
        }
#pragma unroll
        for (int p = 0; p < 8; p++) {
            int r = brow + p * 8;
            float4 v = *(const float4*)(B + (size_t)(k0 + r) * Nc + col0 + bcol);
            unsigned* d = Bs + r * BS_S + bcol;
            d[0] = f2tf(v.x); d[1] = f2tf(v.y); d[2] = f2tf(v.z); d[3] = f2tf(v.w);
        }
        __syncthreads();
        MMA_CHUNK(As, Bs, warp_m, warp_n, g, t, acc)
    }

    float sc[8], sh[8];
#pragma unroll
    for (int nt = 0; nt < 4; nt++)
#pragma unroll
        for (int hh = 0; hh < 2; hh++) {
            int c = col0 + warp_n * 32 + nt * 8 + 2 * t + hh;
            float s = bn[c] * rsqrtf(bn[3 * Nc + c] + BN_EPS);
            sc[nt * 2 + hh] = s;
            sh[nt * 2 + hh] = bn[Nc + c] + (bias[c] - bn[2 * Nc + c]) * s;
        }
#pragma unroll
    for (int mt = 0; mt < 4; mt++)
#pragma unroll
        for (int half = 0; half < 2; half++) {
            int gr = row0 + warp_m * 64 + mt * 16 + g + 8 * half;
            if (gr >= M) continue;
#pragma unroll
            for (int nt = 0; nt < 4; nt++) {
                float y0 = acc[mt][nt][half * 2 + 0] * sc[nt * 2 + 0] + sh[nt * 2 + 0];
                float y1 = acc[mt][nt][half * 2 + 1] * sc[nt * 2 + 1] + sh[nt * 2 + 1];
                if (relu) { y0 = fmaxf(y0, 0.f); y1 = fmaxf(y1, 0.f); }
                int cb = warp_n * 32 + nt * 8 + 2 * t;
                *(float2*)(C + (size_t)gr * Nc + col0 + cb) = make_float2(y0, y1);
            }
        }
}

// ---------------- W2 GEMM: round-4 tgemm core + fused next-layer epilogue ----------------
// out = bn(t2 @ W2 + b2), K=256, Nc=128, A fp32
// final==1: Cf[gr] = out (fp32, no relu)
// final==0: hin = relu(out) + vnext[batch]; agg = (1+eps_next)*hin   (all fp32)
__global__ __launch_bounds__(256, 2)
void tgemm_w2(const float* __restrict__ A, const float* __restrict__ B,
              int M, const float* __restrict__ bias, const float* __restrict__ bn,
              int final_, float* __restrict__ Cf,
              const float* __restrict__ vnext, const int* __restrict__ batch,
              const float* __restrict__ epsp,
              float* __restrict__ hin, float* __restrict__ agg) {
    extern __shared__ unsigned smem[];
    unsigned* As = smem;
    unsigned* Bs = smem + 128 * AS_S;
    const int tid = threadIdx.x;
    const int lane = tid & 31, wid = tid >> 5;
    const int g = lane >> 2, t = lane & 3;
    const int warp_m = wid & 1, warp_n = wid >> 1;
    const int row0 = blockIdx.x * 128;
    const int arow = tid >> 4, acol = (tid & 15) << 2;
    const int brow = tid >> 5, bcol = (tid & 31) << 2;

    float acc[4][4][4];
#pragma unroll
    for (int mt = 0; mt < 4; mt++)
#pragma unroll
        for (int nt = 0; nt < 4; nt++)
#pragma unroll
            for (int q = 0; q < 4; q++) acc[mt][nt][q] = 0.f;

    for (int k0 = 0; k0 < 256; k0 += 64) {
        __syncthreads();
#pragma unroll
        for (int p = 0; p < 8; p++) {
            int r = arow + p * 16;
            int gr = row0 + r;
            float4 v = make_float4(0.f, 0.f, 0.f, 0.f);
            if (gr < M) v = *(const float4*)(A + (size_t)gr * 256 + k0 + acol);
            unsigned* d = As + r * AS_S + acol;
            d[0] = f2tf(v.x); d[1] = f2tf(v.y); d[2] = f2tf(v.z); d[3] = f2tf(v.w);
        }
#pragma unroll
        for (int p = 0; p < 8; p++) {
            int r = brow + p * 8;
            float4 v = *(const float4*)(B + (size_t)(k0 + r) * 128 + bcol);
            unsigned* d = Bs + r * BS_S + bcol;
            d[0] = f2tf(v.x); d[1] = f2tf(v.y); d[2] = f2tf(v.z); d[3] = f2tf(v.w);
        }
        __syncthreads();
        MMA_CHUNK(As, Bs, warp_m, warp_n, g, t, acc)
    }

    float sc[8], sh[8];
#pragma unroll
    for (int nt = 0; nt < 4; nt++)
#pragma unroll
        for (int hh = 0; hh < 2; hh++) {
            int c = warp_n * 32 + nt * 8 + 2 * t + hh;
            float s = bn[c] * rsqrtf(bn[3 * 128 + c] + BN_EPS);
            sc[nt * 2 + hh] = s;
            sh[nt * 2 + hh] = bn[128 + c] + (bias[c] - bn[2 * 128 + c]) * s;
        }

    float ceps = final_ ? 0.f : (1.0f + __ldg(epsp));
#pragma unroll
    for (int mt = 0; mt < 4; mt++)
#pragma unroll
        for (int half = 0; half < 2; half++) {
            int gr = row0 + warp_m * 64 + mt * 16 + g + 8 * half;
            if (gr >= M) continue;
            if (final_) {
#pragma unroll
                for (int nt = 0; nt < 4; nt++) {
                    float y0 = acc[mt][nt][half * 2 + 0] * sc[nt * 2 + 0] + sh[nt * 2 + 0];
                    float y1 = acc[mt][nt][half * 2 + 1] * sc[nt * 2 + 1] + sh[nt * 2 + 1];
                    int cb = warp_n * 32 + nt * 8 + 2 * t;
                    *(float2*)(Cf + (size_t)gr * 128 + cb) = make_float2(y0, y1);
                }
            } else {
                int b = __ldg(batch + gr);
                const float* vrow = vnext + (size_t)b * 128;
#pragma unroll
                for (int nt = 0; nt < 4; nt++) {
                    int cb = warp_n * 32 + nt * 8 + 2 * t;
                    float y0 = fmaxf(acc[mt][nt][half * 2 + 0] * sc[nt * 2 + 0] + sh[nt * 2 + 0], 0.f);
                    float y1 = fmaxf(acc[mt][nt][half * 2 + 1] * sc[nt * 2 + 1] + sh[nt * 2 + 1], 0.f);
                    float h0 = y0 + __ldg(vrow + cb);
                    float h1 = y1 + __ldg(vrow + cb + 1);
                    *(float2*)(hin + (size_t)gr * 128 + cb) = make_float2(h0, h1);
                    *(float2*)(agg + (size_t)gr * 128 + cb) = make_float2(ceps * h0, ceps * h1);
                }
            }
        }
}

// ---------------- virtual node (round-4 verbatim, fp32 hin) ----------------
__global__ void k_vn_agg(const float* __restrict__ hin, const int* __restrict__ batch,
                         const float* __restrict__ vn, float* __restrict__ vt) {
    int g = blockIdx.x, c = threadIdx.x;
    int lo = 0, hi = NN;
    while (lo < hi) { int m = (lo + hi) >> 1; if (batch[m] < g) lo = m + 1; else hi = m; }
    int start = lo;
    lo = start; hi = NN;
    while (lo < hi) { int m = (lo + hi) >> 1; if (batch[m] < g + 1) lo = m + 1; else hi = m; }
    int end = lo;
    float sum = 0.f;
    for (int i = start; i < end; i++) sum += hin[(size_t)i * DD + c];
    vt[g * DD + c] = sum + vn[g * DD + c];
}

__global__ void k_vn_mlp(const float* __restrict__ vt,
                         const float* __restrict__ W1, const float* __restrict__ b1,
                         const float* __restrict__ bn1,
                         const float* __restrict__ W2, const float* __restrict__ b2,
                         const float* __restrict__ bn2, float* __restrict__ vn) {
    __shared__ float xr[DD];
    __shared__ float tr[2 * DD];
    int g = blockIdx.x, tid = threadIdx.x;
    if (tid < DD) xr[tid] = vt[g * DD + tid];
    __syncthreads();
    float acc = b1[tid];
#pragma unroll 8
    for (int k = 0; k < DD; k++) acc = fmaf(xr[k], W1[(size_t)k * 2 * DD + tid], acc);
    float s = bn1[tid] * rsqrtf(bn1[3 * 2 * DD + tid] + BN_EPS);
    acc = (acc - bn1[2 * 2 * DD + tid]) * s + bn1[2 * DD + tid];
    tr[tid] = fmaxf(acc, 0.f);
    __syncthreads();
    if (tid < DD) {
        float a2 = b2[tid];
#pragma unroll 8
        for (int k = 0; k < 2 * DD; k++) a2 = fmaf(tr[k], W2[(size_t)k * DD + tid], a2);
        float s2 = bn2[tid] * rsqrtf(bn2[3 * DD + tid] + BN_EPS);
        a2 = (a2 - bn2[2 * DD + tid]) * s2 + bn2[DD + tid];
        vn[g * DD + tid] = fmaxf(a2, 0.f);
    }
}

// ---------------- host launcher ----------------
extern "C" void kernel_launch(void* const* d_in, const int* in_sizes, int n_in,
                              void* d_out, int out_size) {
    const int*   x_node     = (const int*)d_in[0];
    const int*   edge_index = (const int*)d_in[1];
    const float* edge_attr  = (const float*)d_in[2];
    const int*   batch      = (const int*)d_in[3];
    const int*   pos_index  = (const int*)d_in[4];
    const float* pos_enc    = (const float*)d_in[5];
    const int*   pos_batch  = (const int*)d_in[6];
    const float* node_emb   = (const float*)d_in[7];
    const float* z_init     = (const float*)d_in[8];
    const float* ze_bn1     = (const float*)d_in[9];
    const float* ze_W       = (const float*)d_in[10];
    const float* ze_b       = (const float*)d_in[11];
    const float* ze_bn2     = (const float*)d_in[12];
    const float* vn_emb     = (const float*)d_in[13];
    const float* conv_We    = (const float*)d_in[14];
    const float* conv_be    = (const float*)d_in[15];
    const float* conv_Wp    = (const float*)d_in[16];
    const float* conv_bp    = (const float*)d_in[17];
    const float* conv_W1    = (const float*)d_in[18];
    const float* conv_b1    = (const float*)d_in[19];
    const float* conv_bn    = (const float*)d_in[20];
    const float* conv_W2    = (const float*)d_in[21];
    const float* conv_b2    = (const float*)d_in[22];
    const float* conv_eps   = (const float*)d_in[23];
    const float* layer_bn   = (const float*)d_in[24];
    const float* vn_W1      = (const float*)d_in[25];
    const float* vn_b1      = (const float*)d_in[26];
    const float* vn_bn1     = (const float*)d_in[27];
    const float* vn_W2      = (const float*)d_in[28];
    const float* vn_b2      = (const float*)d_in[29];
    const float* vn_bn2     = (const float*)d_in[30];

    __half* z2;
    float *hin, *agg, *t2, *vn, *vt;
    cudaGetSymbolAddress((void**)&z2,  g_z2);
    cudaGetSymbolAddress((void**)&hin, g_hin);
    cudaGetSymbolAddress((void**)&agg, g_agg);
    cudaGetSymbolAddress((void**)&t2,  g_t2);
    cudaGetSymbolAddress((void**)&vn,  g_vn);
    cudaGetSymbolAddress((void**)&vt,  g_vt);

    cudaFuncSetAttribute(k_zenc, cudaFuncAttributeMaxDynamicSharedMemorySize, TG_SMEM);
    cudaFuncSetAttribute(k_edge_fused, cudaFuncAttributeMaxDynamicSharedMemorySize, TG_SMEM);
    cudaFuncSetAttribute(tgemm, cudaFuncAttributeMaxDynamicSharedMemorySize, TG_SMEM);
    cudaFuncSetAttribute(tgemm_w2, cudaFuncAttributeMaxDynamicSharedMemorySize, TG_SMEM);

    float* h = (float*)d_out;

    k_init_vn<<<(GG * DD + 255) / 256, 256>>>(vn_emb, vn);
    k_init_hin<<<(NN * 32 + 255) / 256, 256>>>(x_node, node_emb, vn_emb, conv_eps, hin, agg);
    k_zenc<<<EE / 128, 256, TG_SMEM>>>(pos_index, pos_enc, pos_batch, z_init,
                                       ze_bn1, ze_b, ze_bn2, ze_W, z2);

    const int* srcp = edge_index;
    const int* dstp = edge_index + EE;
    const int nblk = (NN + 127) / 128;

    for (int l = 0; l < LL; l++) {
        k_edge_fused<<<EE / 128, 256, TG_SMEM>>>(z2, conv_Wp + (size_t)l * DD * DD,
                                                 conv_bp + l * DD, conv_be + l * DD,
                                                 edge_attr, conv_We + (size_t)l * 7 * DD,
                                                 srcp, dstp, hin, agg);
        if (l < LL - 1) {
            // vn_{l+1} computed from hin_l before W2 epilogue consumes it
            k_vn_agg<<<GG, DD>>>(hin, batch, vn, vt);
            k_vn_mlp<<<GG, 256>>>(vt, vn_W1 + (size_t)l * DD * 2 * DD, vn_b1 + l * 2 * DD,
                                  vn_bn1 + (size_t)l * 4 * 2 * DD,
                                  vn_W2 + (size_t)l * 2 * DD * DD, vn_b2 + l * DD,
                                  vn_bn2 + (size_t)l * 4 * DD, vn);
        }
        tgemm<<<dim3(nblk, 2), 256, TG_SMEM>>>(agg, conv_W1 + (size_t)l * DD * 2 * DD,
                                               NN, DD, 2 * DD,
                                               conv_b1 + l * 2 * DD,
                                               conv_bn + (size_t)l * 4 * 2 * DD, 1, t2);
        int fin = (l == LL - 1) ? 1 : 0;
        tgemm_w2<<<dim3(nblk, 1), 256, TG_SMEM>>>(t2, conv_W2 + (size_t)l * 2 * DD * DD,
                                                  NN, conv_b2 + l * DD,
                                                  layer_bn + (size_t)l * 4 * DD,
                                                  fin, h, vn, batch,
                                                  conv_eps + (fin ? l : l + 1),
                                                  hin, agg);
    }
}